// round 10
// baseline (speedup 1.0000x reference)
#include <cuda_runtime.h>
#include <cuda_bf16.h>
#include <math.h>

// Problem dims (fixed by the reference)
#define T_STEPS 512
#define BATCH   256
#define DIM     1024
#define HID     1024
#define OUTD    5

// R9 recurrence geometry: 256 CTAs = 8 m-groups(32) x 32 n-tiles(32),
// 128 threads (4 warps, warp tile 16x16), 80KB smem -> 2 CTAs/SM.
#define GRID_P  256
#define MT      32
#define NT      32

// Scratch
__device__ float          g_E[(size_t)T_STEPS * BATCH * HID];     // fp32 input proj
__device__ __nv_bfloat16  g_hbf[2][(size_t)BATCH * HID];          // bf16 h transport
__device__ float          g_hfinal[(size_t)BATCH * HID];          // fp32 final h
__device__ unsigned       g_grp[8][32];                           // per-m-group barrier ctrs

// ---------------------------------------------------------------------------
__device__ __forceinline__ void mma_bf16(float d[4],
                                         unsigned a0, unsigned a1,
                                         unsigned a2, unsigned a3,
                                         unsigned b0, unsigned b1)
{
    asm volatile(
        "mma.sync.aligned.m16n8k16.row.col.f32.bf16.bf16.f32 "
        "{%0,%1,%2,%3}, {%4,%5,%6,%7}, {%8,%9}, {%0,%1,%2,%3};"
        : "+f"(d[0]), "+f"(d[1]), "+f"(d[2]), "+f"(d[3])
        : "r"(a0), "r"(a1), "r"(a2), "r"(a3), "r"(b0), "r"(b1));
}

__device__ __forceinline__ float sigmoidf_fast(float x)
{
    return 1.0f / (1.0f + __expf(-x));
}

// ---------------------------------------------------------------------------
// E = x @ W_in^T + b_in, single-pass bf16 tensor-core GEMM (validated R7/R8).
// ---------------------------------------------------------------------------
__global__ void __launch_bounds__(256, 2)
egemm_bf16(const float* __restrict__ X,     // [131072, 1024]
           const float* __restrict__ Wg,    // [1024, 1024]
           const float* __restrict__ bias,  // [1024]
           float* __restrict__ E)
{
    extern __shared__ unsigned es[];
    unsigned* Ah = es;              // 8192 words (32KB)
    unsigned* Bh = es + 8192;       // 4096 words (16KB)

    const int tid  = threadIdx.x;
    const int lane = tid & 31;
    const int w    = tid >> 5;
    const int qid  = lane >> 2;
    const int c    = lane & 3;
    const int g    = w >> 1;
    const int subm = (w & 1) * 16;

    const int n0 = blockIdx.x * 64;
    const int m0 = blockIdx.y * 128;

    const int srow = tid >> 3;
    const int ssl  = tid & 7;
    const int sx   = ssl & 3;

    float acc[4][2][4];
    #pragma unroll
    for (int a = 0; a < 4; a++)
        #pragma unroll
        for (int b = 0; b < 2; b++)
            #pragma unroll
            for (int d = 0; d < 4; d++) acc[a][b][d] = 0.0f;

    for (int ch = 0; ch < 8; ch++) {
        __syncthreads();
        const float* xbase = X + (size_t)(m0 + srow) * 1024 + ch * 128 + ssl * 16;
        #pragma unroll
        for (int jj = 0; jj < 4; jj++) {
            const float4* p = (const float4*)(xbase + (size_t)jj * 32 * 1024);
            float4 f0 = p[0], f1 = p[1], f2 = p[2], f3 = p[3];
            unsigned h[8];
            {
                __nv_bfloat162 b0 = __float22bfloat162_rn(make_float2(f0.x, f0.y));
                __nv_bfloat162 b1 = __float22bfloat162_rn(make_float2(f0.z, f0.w));
                __nv_bfloat162 b2 = __float22bfloat162_rn(make_float2(f1.x, f1.y));
                __nv_bfloat162 b3 = __float22bfloat162_rn(make_float2(f1.z, f1.w));
                __nv_bfloat162 b4 = __float22bfloat162_rn(make_float2(f2.x, f2.y));
                __nv_bfloat162 b5 = __float22bfloat162_rn(make_float2(f2.z, f2.w));
                __nv_bfloat162 b6 = __float22bfloat162_rn(make_float2(f3.x, f3.y));
                __nv_bfloat162 b7 = __float22bfloat162_rn(make_float2(f3.z, f3.w));
                h[0] = *(unsigned*)&b0; h[1] = *(unsigned*)&b1;
                h[2] = *(unsigned*)&b2; h[3] = *(unsigned*)&b3;
                h[4] = *(unsigned*)&b4; h[5] = *(unsigned*)&b5;
                h[6] = *(unsigned*)&b6; h[7] = *(unsigned*)&b7;
            }
            uint2* dh = (uint2*)&Ah[jj * 2048 + ssl * 256 + srow * 8];
            dh[0 ^ sx] = make_uint2(h[0], h[4]);
            dh[1 ^ sx] = make_uint2(h[1], h[5]);
            dh[2 ^ sx] = make_uint2(h[2], h[6]);
            dh[3 ^ sx] = make_uint2(h[3], h[7]);
        }
        #pragma unroll
        for (int jj = 0; jj < 2; jj++) {
            int nrow = srow + jj * 32;
            const float4* p = (const float4*)(Wg + (size_t)(n0 + nrow) * 1024
                                              + ch * 128 + ssl * 16);
            float4 f0 = p[0], f1 = p[1], f2 = p[2], f3 = p[3];
            unsigned h[8];
            {
                __nv_bfloat162 b0 = __float22bfloat162_rn(make_float2(f0.x, f0.y));
                __nv_bfloat162 b1 = __float22bfloat162_rn(make_float2(f0.z, f0.w));
                __nv_bfloat162 b2 = __float22bfloat162_rn(make_float2(f1.x, f1.y));
                __nv_bfloat162 b3 = __float22bfloat162_rn(make_float2(f1.z, f1.w));
                __nv_bfloat162 b4 = __float22bfloat162_rn(make_float2(f2.x, f2.y));
                __nv_bfloat162 b5 = __float22bfloat162_rn(make_float2(f2.z, f2.w));
                __nv_bfloat162 b6 = __float22bfloat162_rn(make_float2(f3.x, f3.y));
                __nv_bfloat162 b7 = __float22bfloat162_rn(make_float2(f3.z, f3.w));
                h[0] = *(unsigned*)&b0; h[1] = *(unsigned*)&b1;
                h[2] = *(unsigned*)&b2; h[3] = *(unsigned*)&b3;
                h[4] = *(unsigned*)&b4; h[5] = *(unsigned*)&b5;
                h[6] = *(unsigned*)&b6; h[7] = *(unsigned*)&b7;
            }
            uint2* dh = (uint2*)&Bh[ssl * 512 + nrow * 8];
            dh[0 ^ sx] = make_uint2(h[0], h[4]);
            dh[1 ^ sx] = make_uint2(h[1], h[5]);
            dh[2 ^ sx] = make_uint2(h[2], h[6]);
            dh[3 ^ sx] = make_uint2(h[3], h[7]);
        }
        __syncthreads();

        #pragma unroll
        for (int sl = 0; sl < 8; sl++) {
            int axw = g * 2048 + sl * 256 + (subm + qid) * 8 + 2 * (c ^ (sl & 3));
            uint2 ah0 = *(const uint2*)&Ah[axw];
            uint2 ah1 = *(const uint2*)&Ah[axw + 64];
            #pragma unroll
            for (int ng = 0; ng < 4; ng++) {
                int bxw = sl * 512 + ng * 128 + qid * 8 + 2 * (c ^ (sl & 3));
                uint2 bh0 = *(const uint2*)&Bh[bxw];
                uint2 bh1 = *(const uint2*)&Bh[bxw + 64];
                mma_bf16(acc[ng][0], ah0.x, ah1.x, ah0.y, ah1.y, bh0.x, bh0.y);
                mma_bf16(acc[ng][1], ah0.x, ah1.x, ah0.y, ah1.y, bh1.x, bh1.y);
            }
        }
    }

    const int mrow = m0 + w * 16 + qid;
    #pragma unroll
    for (int ng = 0; ng < 4; ng++) {
        #pragma unroll
        for (int hh = 0; hh < 2; hh++) {
            int col = n0 + ng * 16 + hh * 8 + 2 * c;
            float2 b2 = *(const float2*)(bias + col);
            float2 o0, o1;
            o0.x = acc[ng][hh][0] + b2.x; o0.y = acc[ng][hh][1] + b2.y;
            o1.x = acc[ng][hh][2] + b2.x; o1.y = acc[ng][hh][3] + b2.y;
            *(float2*)&E[(size_t)mrow * 1024 + col]       = o0;
            *(float2*)&E[(size_t)(mrow + 8) * 1024 + col] = o1;
        }
    }
}

// ---------------------------------------------------------------------------
__global__ void h0_to_bf16(const float* __restrict__ h0)
{
    int i = blockIdx.x * 256 + threadIdx.x;
    g_hbf[1][i] = __float2bfloat16(h0[i]);
}

// Dummy launch: shifts ncu's fixed capture slot onto rnn_persistent.
__global__ void ncu_shift_dummy() {}

// ---------------------------------------------------------------------------
// Per-m-group barrier: 32 CTAs, release/acquire atomics, monotonic counter.
// ---------------------------------------------------------------------------
__device__ __forceinline__ void group_barrier(int grp, unsigned target)
{
    __syncthreads();
    if (threadIdx.x == 0) {
        unsigned* ctr = &g_grp[grp][0];
        asm volatile("red.release.gpu.global.add.u32 [%0], %1;"
                     :: "l"(ctr), "r"(1u) : "memory");
        unsigned v;
        do {
            asm volatile("ld.acquire.gpu.global.u32 %0, [%1];"
                         : "=r"(v) : "l"(ctr) : "memory");
        } while (v < target);
    }
    __syncthreads();
}

// ---------------------------------------------------------------------------
// Persistent recurrence, R9: 32m x 32n CTA tile, 4 warps (16x16 each),
// 80KB smem -> 2 co-resident CTAs/SM so one CTA's HMMA stream hides the
// other's load/stage/epilogue/barrier phases. Fragment layout identical to
// the validated scheme; Ws slice stride 256 words (NT=32).
// smem: Ws 64KB (64 slices x 256 words) + As 2 x 8KB double-buffered chunks.
// ---------------------------------------------------------------------------
__global__ void __launch_bounds__(128, 2)
rnn_persistent(const float* __restrict__ W_h,
               const float* __restrict__ b_h)
{
    extern __shared__ unsigned smw[];
    unsigned* Ws = smw;              // 16384 words (64KB)
    unsigned* As = smw + 16384;      // 2 x 2048 words (2 x 8KB)

    const int tid  = threadIdx.x;
    const int lane = tid & 31;
    const int w    = tid >> 5;       // 0..3
    const int qid  = lane >> 2;
    const int c    = lane & 3;
    const int mw   = (w >> 1) * 16;  // warp m offset (0/16)
    const int nw   = (w & 1) * 16;   // warp n offset (0/16)
    const int cta  = blockIdx.x;
    const int grp  = cta >> 5;       // 8 groups of 32 CTAs
    const int m0   = grp * MT;
    const int n0   = (cta & 31) * NT;

    // ---- fill Ws (once): W_h rows n0..n0+31, fragment-shuffled bf16 ----
    for (int i = tid; i < NT * 512; i += 128) {
        int n  = i >> 9;             // 0..31
        int kp = i & 511;
        int k  = kp * 2;
        int s  = k >> 4;             // 0..63
        int p  = (k & 15) >> 1;
        float2 wv = *(const float2*)(W_h + (size_t)(n0 + n) * HID + k);
        __nv_bfloat162 bb = __float22bfloat162_rn(wv);
        Ws[s * 256 + n * 8 + (p & 3) * 2 + (p >> 2)] = *(unsigned*)&bb;
    }
    const float2 bh0 = *(const float2*)(b_h + n0 + nw + 2 * c);
    const float2 bh1 = *(const float2*)(b_h + n0 + nw + 8 + 2 * c);
    __syncthreads();

    // staging map: 128 threads, each handles row srow, slices ssl2, ssl2+1
    const int srow = tid >> 2;           // 0..31
    const int ssl2 = (tid & 3) * 2;      // 0,2,4,6

    for (int t = 0; t < T_STEPS; t++) {
        const __nv_bfloat16* hin  = g_hbf[(t + 1) & 1];
        __nv_bfloat16*       hout = g_hbf[t & 1];

        // epilogue operands (prefetch, overlap with step)
        const float* eb = g_E + ((size_t)t * BATCH + m0 + mw + qid) * HID
                              + n0 + nw + 2 * c;
        float2 e00 = __ldg((const float2*)eb);
        float2 e01 = __ldg((const float2*)(eb + 8));
        float2 e10 = __ldg((const float2*)(eb + 8 * HID));
        float2 e11 = __ldg((const float2*)(eb + 8 * HID + 8));

        const __nv_bfloat16* gsrc = hin + (size_t)(m0 + srow) * HID;

        // prefetch chunk 0 (2 slices x 2 int4)
        int4 v0a = __ldcg((const int4*)(gsrc + ssl2 * 16));
        int4 v0b = __ldcg((const int4*)(gsrc + ssl2 * 16 + 8));
        int4 v1a = __ldcg((const int4*)(gsrc + ssl2 * 16 + 16));
        int4 v1b = __ldcg((const int4*)(gsrc + ssl2 * 16 + 24));
        {
            int sxa = ssl2 & 3, sxb = (ssl2 + 1) & 3;
            uint2* da = (uint2*)(As + ssl2 * 256 + srow * 8);
            uint2* db = (uint2*)(As + (ssl2 + 1) * 256 + srow * 8);
            da[0 ^ sxa] = make_uint2(v0a.x, v0b.x);
            da[1 ^ sxa] = make_uint2(v0a.y, v0b.y);
            da[2 ^ sxa] = make_uint2(v0a.z, v0b.z);
            da[3 ^ sxa] = make_uint2(v0a.w, v0b.w);
            db[0 ^ sxb] = make_uint2(v1a.x, v1b.x);
            db[1 ^ sxb] = make_uint2(v1a.y, v1b.y);
            db[2 ^ sxb] = make_uint2(v1a.z, v1b.z);
            db[3 ^ sxb] = make_uint2(v1a.w, v1b.w);
        }
        __syncthreads();

        float d0[4][4];
        float d1[4][4];
        #pragma unroll
        for (int cc = 0; cc < 4; cc++)
            #pragma unroll
            for (int j = 0; j < 4; j++) { d0[cc][j] = 0.f; d1[cc][j] = 0.f; }

        #pragma unroll 1
        for (int ch = 0; ch < 8; ch++) {
            if (ch < 7) {
                const __nv_bfloat16* gn = gsrc + (ch + 1) * 128 + ssl2 * 16;
                v0a = __ldcg((const int4*)(gn));
                v0b = __ldcg((const int4*)(gn + 8));
                v1a = __ldcg((const int4*)(gn + 16));
                v1b = __ldcg((const int4*)(gn + 24));
            }
            const unsigned* Ab = As + (ch & 1) * 2048;
            #pragma unroll
            for (int sl = 0; sl < 8; sl++) {
                const int cc = sl & 3;
                int aoff = sl * 256 + (mw + qid) * 8 + 2 * (c ^ (sl & 3));
                uint2 aLo = *(const uint2*)(Ab + aoff);
                uint2 aHi = *(const uint2*)(Ab + aoff + 64);
                const unsigned* Wb = Ws + (ch * 8 + sl) * 256 + (nw + qid) * 8 + 2 * c;
                uint2 b0 = *(const uint2*)(Wb);
                uint2 b1 = *(const uint2*)(Wb + 64);
                mma_bf16(d0[cc], aLo.x, aHi.x, aLo.y, aHi.y, b0.x, b0.y);
                mma_bf16(d1[cc], aLo.x, aHi.x, aLo.y, aHi.y, b1.x, b1.y);
            }
            if (ch < 7) {
                unsigned* Bn = As + ((ch + 1) & 1) * 2048;
                int sxa = ssl2 & 3, sxb = (ssl2 + 1) & 3;
                uint2* da = (uint2*)(Bn + ssl2 * 256 + srow * 8);
                uint2* db = (uint2*)(Bn + (ssl2 + 1) * 256 + srow * 8);
                da[0 ^ sxa] = make_uint2(v0a.x, v0b.x);
                da[1 ^ sxa] = make_uint2(v0a.y, v0b.y);
                da[2 ^ sxa] = make_uint2(v0a.z, v0b.z);
                da[3 ^ sxa] = make_uint2(v0a.w, v0b.w);
                db[0 ^ sxb] = make_uint2(v1a.x, v1b.x);
                db[1 ^ sxb] = make_uint2(v1a.y, v1b.y);
                db[2 ^ sxb] = make_uint2(v1a.z, v1b.z);
                db[3 ^ sxb] = make_uint2(v1a.w, v1b.w);
            }
            __syncthreads();
        }

        // pairwise reduction of the 4 chains
        float f0[4], f1[4];
        #pragma unroll
        for (int j = 0; j < 4; j++) {
            f0[j] = (d0[0][j] + d0[1][j]) + (d0[2][j] + d0[3][j]);
            f1[j] = (d1[0][j] + d1[1][j]) + (d1[2][j] + d1[3][j]);
        }

        // ---- epilogue: z = f + b_h + E; h = sigmoid(z) (all fp32) ----
        float s00x = sigmoidf_fast(f0[0] + bh0.x + e00.x);
        float s00y = sigmoidf_fast(f0[1] + bh0.y + e00.y);
        float s10x = sigmoidf_fast(f0[2] + bh0.x + e10.x);
        float s10y = sigmoidf_fast(f0[3] + bh0.y + e10.y);
        float s01x = sigmoidf_fast(f1[0] + bh1.x + e01.x);
        float s01y = sigmoidf_fast(f1[1] + bh1.y + e01.y);
        float s11x = sigmoidf_fast(f1[2] + bh1.x + e11.x);
        float s11y = sigmoidf_fast(f1[3] + bh1.y + e11.y);

        __nv_bfloat16* ho = hout + (size_t)(m0 + mw + qid) * HID + n0 + nw + 2 * c;
        *(__nv_bfloat162*)(ho)               = __float22bfloat162_rn(make_float2(s00x, s00y));
        *(__nv_bfloat162*)(ho + 8)           = __float22bfloat162_rn(make_float2(s01x, s01y));
        *(__nv_bfloat162*)(ho + 8 * HID)     = __float22bfloat162_rn(make_float2(s10x, s10y));
        *(__nv_bfloat162*)(ho + 8 * HID + 8) = __float22bfloat162_rn(make_float2(s11x, s11y));

        if (t == T_STEPS - 1) {
            float* hf = g_hfinal + (size_t)(m0 + mw + qid) * HID + n0 + nw + 2 * c;
            *(float2*)(hf)               = make_float2(s00x, s00y);
            *(float2*)(hf + 8)           = make_float2(s01x, s01y);
            *(float2*)(hf + 8 * HID)     = make_float2(s10x, s10y);
            *(float2*)(hf + 8 * HID + 8) = make_float2(s11x, s11y);
        } else {
            group_barrier(grp, 32u * (t + 1));
        }
    }
}

// ---------------------------------------------------------------------------
// Final head (all 128 threads participate in the dot product)
// ---------------------------------------------------------------------------
__global__ void finalize_kernel(const float* __restrict__ h,
                                const float* __restrict__ state_in,
                                const float* __restrict__ W_o,
                                const float* __restrict__ b_o,
                                float* __restrict__ out)
{
    const int b    = blockIdx.x;
    const int tid  = threadIdx.x;
    const int lane = tid & 31;
    const int wid  = tid >> 5;

    __shared__ float red[4][OUTD];
    __shared__ float logits[OUTD];

    float acc[OUTD];
    #pragma unroll
    for (int o = 0; o < OUTD; o++) acc[o] = 0.0f;
    for (int k = tid; k < HID; k += 128) {
        float hv = h[(size_t)b * HID + k];
        #pragma unroll
        for (int o = 0; o < OUTD; o++)
            acc[o] += hv * W_o[(size_t)o * HID + k];
    }
    #pragma unroll
    for (int o = 0; o < OUTD; o++) {
        float v = acc[o];
        #pragma unroll
        for (int s = 16; s > 0; s >>= 1)
            v += __shfl_xor_sync(0xffffffff, v, s);
        if (lane == 0) red[wid][o] = v;
    }
    __syncthreads();

    if (tid == 0) {
        #pragma unroll
        for (int o = 0; o < OUTD; o++)
            logits[o] = red[0][o] + red[1][o] + red[2][o] + red[3][o] + b_o[o];
        float m = logits[0];
        #pragma unroll
        for (int o = 1; o < OUTD; o++) m = fmaxf(m, logits[o]);
        float s = 0.0f;
        #pragma unroll
        for (int o = 0; o < OUTD; o++) s += expf(logits[o] - m);
        float lse = m + logf(s);
        #pragma unroll
        for (int o = 0; o < OUTD; o++)
            out[(size_t)b * OUTD + o] = logits[o] - lse;
    }

    float* hid_out = out + (size_t)BATCH * OUTD;
    float* st_out  = hid_out + (size_t)BATCH * HID;
    for (int k = tid; k < HID; k += blockDim.x) {
        hid_out[(size_t)b * HID + k] = h[(size_t)b * HID + k];
        st_out[(size_t)b * HID + k]  = state_in[(size_t)b * HID + k];
    }
}

extern "C" void kernel_launch(void* const* d_in, const int* in_sizes, int n_in,
                              void* d_out, int out_size)
{
    const float* x    = (const float*)d_in[0];
    const float* h0   = (const float*)d_in[1];
    const float* st   = (const float*)d_in[2];
    const float* W_in = (const float*)d_in[3];
    const float* b_in = (const float*)d_in[4];
    const float* W_h  = (const float*)d_in[5];
    const float* b_h  = (const float*)d_in[6];
    const float* W_o  = (const float*)d_in[7];
    const float* b_o  = (const float*)d_in[8];
    float* out = (float*)d_out;

    float* Eptr = nullptr;
    float* hfin = nullptr;
    unsigned* grpptr = nullptr;
    cudaGetSymbolAddress((void**)&Eptr, g_E);
    cudaGetSymbolAddress((void**)&hfin, g_hfinal);
    cudaGetSymbolAddress((void**)&grpptr, g_grp);

    cudaMemsetAsync(grpptr, 0, 8 * 32 * sizeof(unsigned));

    // 0) h0 -> bf16 transport buffer
    h0_to_bf16<<<(BATCH * HID) / 256, 256>>>(h0);

    // 1) E = x @ W_in^T + b_in (single-pass bf16, fp32 accumulate)
    {
        const int smem_bytes = 12288 * sizeof(unsigned);  // 48KB
        cudaFuncSetAttribute(egemm_bf16,
                             cudaFuncAttributeMaxDynamicSharedMemorySize, smem_bytes);
        dim3 grid(HID / 64, (T_STEPS * BATCH) / 128);
        egemm_bf16<<<grid, 256, smem_bytes>>>(x, W_in, b_in, Eptr);
    }

    // 1.5) shift ncu's capture slot onto rnn_persistent
    ncu_shift_dummy<<<1, 32>>>();

    // 2) Persistent recurrence (R9: 2 CTAs/SM overlap)
    {
        const int smem_bytes = (16384 + 4096) * sizeof(unsigned);  // 80KB
        cudaFuncSetAttribute(rnn_persistent,
                             cudaFuncAttributeMaxDynamicSharedMemorySize, smem_bytes);
        rnn_persistent<<<GRID_P, 128, smem_bytes>>>(W_h, b_h);
    }

    // 3) Head + output tuple
    finalize_kernel<<<BATCH, 128>>>(hfin, st, W_o, b_o, out);
}

// round 11
// speedup vs baseline: 1.3094x; 1.3094x over previous
#include <cuda_runtime.h>
#include <cuda_bf16.h>
#include <math.h>

// Problem dims (fixed by the reference)
#define T_STEPS 512
#define BATCH   256
#define DIM     1024
#define HID     1024
#define OUTD    5

// Recurrence geometry (R8 shell): 128 CTAs = 8 m-groups(32) x 16 n-tiles(64)
#define GRID_P  128
#define MT      32
#define NT      64
#define RSTR    68            // padded fp32 row stride in reduction buffer
#define RKQ     (32 * RSTR)   // per-k-quarter stride (2176 words)

// Scratch
__device__ float          g_E[(size_t)T_STEPS * BATCH * HID];     // fp32 input proj
__device__ __nv_bfloat16  g_hbf[2][(size_t)BATCH * HID];          // bf16 h transport
__device__ float          g_hfinal[(size_t)BATCH * HID];          // fp32 final h
__device__ unsigned       g_grp[8][32];                           // per-m-group barrier ctrs

// ---------------------------------------------------------------------------
__device__ __forceinline__ void mma_bf16(float d[4],
                                         unsigned a0, unsigned a1,
                                         unsigned a2, unsigned a3,
                                         unsigned b0, unsigned b1)
{
    asm volatile(
        "mma.sync.aligned.m16n8k16.row.col.f32.bf16.bf16.f32 "
        "{%0,%1,%2,%3}, {%4,%5,%6,%7}, {%8,%9}, {%0,%1,%2,%3};"
        : "+f"(d[0]), "+f"(d[1]), "+f"(d[2]), "+f"(d[3])
        : "r"(a0), "r"(a1), "r"(a2), "r"(a3), "r"(b0), "r"(b1));
}

__device__ __forceinline__ float sigmoidf_fast(float x)
{
    return 1.0f / (1.0f + __expf(-x));
}

// ---------------------------------------------------------------------------
// E = x @ W_in^T + b_in, single-pass bf16 tensor-core GEMM (validated R7/R8).
// ---------------------------------------------------------------------------
__global__ void __launch_bounds__(256, 2)
egemm_bf16(const float* __restrict__ X,     // [131072, 1024]
           const float* __restrict__ Wg,    // [1024, 1024]
           const float* __restrict__ bias,  // [1024]
           float* __restrict__ E)
{
    extern __shared__ unsigned es[];
    unsigned* Ah = es;              // 8192 words (32KB)
    unsigned* Bh = es + 8192;       // 4096 words (16KB)

    const int tid  = threadIdx.x;
    const int lane = tid & 31;
    const int w    = tid >> 5;
    const int qid  = lane >> 2;
    const int c    = lane & 3;
    const int g    = w >> 1;
    const int subm = (w & 1) * 16;

    const int n0 = blockIdx.x * 64;
    const int m0 = blockIdx.y * 128;

    const int srow = tid >> 3;
    const int ssl  = tid & 7;
    const int sx   = ssl & 3;

    float acc[4][2][4];
    #pragma unroll
    for (int a = 0; a < 4; a++)
        #pragma unroll
        for (int b = 0; b < 2; b++)
            #pragma unroll
            for (int d = 0; d < 4; d++) acc[a][b][d] = 0.0f;

    for (int ch = 0; ch < 8; ch++) {
        __syncthreads();
        const float* xbase = X + (size_t)(m0 + srow) * 1024 + ch * 128 + ssl * 16;
        #pragma unroll
        for (int jj = 0; jj < 4; jj++) {
            const float4* p = (const float4*)(xbase + (size_t)jj * 32 * 1024);
            float4 f0 = p[0], f1 = p[1], f2 = p[2], f3 = p[3];
            unsigned h[8];
            {
                __nv_bfloat162 b0 = __float22bfloat162_rn(make_float2(f0.x, f0.y));
                __nv_bfloat162 b1 = __float22bfloat162_rn(make_float2(f0.z, f0.w));
                __nv_bfloat162 b2 = __float22bfloat162_rn(make_float2(f1.x, f1.y));
                __nv_bfloat162 b3 = __float22bfloat162_rn(make_float2(f1.z, f1.w));
                __nv_bfloat162 b4 = __float22bfloat162_rn(make_float2(f2.x, f2.y));
                __nv_bfloat162 b5 = __float22bfloat162_rn(make_float2(f2.z, f2.w));
                __nv_bfloat162 b6 = __float22bfloat162_rn(make_float2(f3.x, f3.y));
                __nv_bfloat162 b7 = __float22bfloat162_rn(make_float2(f3.z, f3.w));
                h[0] = *(unsigned*)&b0; h[1] = *(unsigned*)&b1;
                h[2] = *(unsigned*)&b2; h[3] = *(unsigned*)&b3;
                h[4] = *(unsigned*)&b4; h[5] = *(unsigned*)&b5;
                h[6] = *(unsigned*)&b6; h[7] = *(unsigned*)&b7;
            }
            uint2* dh = (uint2*)&Ah[jj * 2048 + ssl * 256 + srow * 8];
            dh[0 ^ sx] = make_uint2(h[0], h[4]);
            dh[1 ^ sx] = make_uint2(h[1], h[5]);
            dh[2 ^ sx] = make_uint2(h[2], h[6]);
            dh[3 ^ sx] = make_uint2(h[3], h[7]);
        }
        #pragma unroll
        for (int jj = 0; jj < 2; jj++) {
            int nrow = srow + jj * 32;
            const float4* p = (const float4*)(Wg + (size_t)(n0 + nrow) * 1024
                                              + ch * 128 + ssl * 16);
            float4 f0 = p[0], f1 = p[1], f2 = p[2], f3 = p[3];
            unsigned h[8];
            {
                __nv_bfloat162 b0 = __float22bfloat162_rn(make_float2(f0.x, f0.y));
                __nv_bfloat162 b1 = __float22bfloat162_rn(make_float2(f0.z, f0.w));
                __nv_bfloat162 b2 = __float22bfloat162_rn(make_float2(f1.x, f1.y));
                __nv_bfloat162 b3 = __float22bfloat162_rn(make_float2(f1.z, f1.w));
                __nv_bfloat162 b4 = __float22bfloat162_rn(make_float2(f2.x, f2.y));
                __nv_bfloat162 b5 = __float22bfloat162_rn(make_float2(f2.z, f2.w));
                __nv_bfloat162 b6 = __float22bfloat162_rn(make_float2(f3.x, f3.y));
                __nv_bfloat162 b7 = __float22bfloat162_rn(make_float2(f3.z, f3.w));
                h[0] = *(unsigned*)&b0; h[1] = *(unsigned*)&b1;
                h[2] = *(unsigned*)&b2; h[3] = *(unsigned*)&b3;
                h[4] = *(unsigned*)&b4; h[5] = *(unsigned*)&b5;
                h[6] = *(unsigned*)&b6; h[7] = *(unsigned*)&b7;
            }
            uint2* dh = (uint2*)&Bh[ssl * 512 + nrow * 8];
            dh[0 ^ sx] = make_uint2(h[0], h[4]);
            dh[1 ^ sx] = make_uint2(h[1], h[5]);
            dh[2 ^ sx] = make_uint2(h[2], h[6]);
            dh[3 ^ sx] = make_uint2(h[3], h[7]);
        }
        __syncthreads();

        #pragma unroll
        for (int sl = 0; sl < 8; sl++) {
            int axw = g * 2048 + sl * 256 + (subm + qid) * 8 + 2 * (c ^ (sl & 3));
            uint2 ah0 = *(const uint2*)&Ah[axw];
            uint2 ah1 = *(const uint2*)&Ah[axw + 64];
            #pragma unroll
            for (int ng = 0; ng < 4; ng++) {
                int bxw = sl * 512 + ng * 128 + qid * 8 + 2 * (c ^ (sl & 3));
                uint2 bh0 = *(const uint2*)&Bh[bxw];
                uint2 bh1 = *(const uint2*)&Bh[bxw + 64];
                mma_bf16(acc[ng][0], ah0.x, ah1.x, ah0.y, ah1.y, bh0.x, bh0.y);
                mma_bf16(acc[ng][1], ah0.x, ah1.x, ah0.y, ah1.y, bh1.x, bh1.y);
            }
        }
    }

    const int mrow = m0 + w * 16 + qid;
    #pragma unroll
    for (int ng = 0; ng < 4; ng++) {
        #pragma unroll
        for (int hh = 0; hh < 2; hh++) {
            int col = n0 + ng * 16 + hh * 8 + 2 * c;
            float2 b2 = *(const float2*)(bias + col);
            float2 o0, o1;
            o0.x = acc[ng][hh][0] + b2.x; o0.y = acc[ng][hh][1] + b2.y;
            o1.x = acc[ng][hh][2] + b2.x; o1.y = acc[ng][hh][3] + b2.y;
            *(float2*)&E[(size_t)mrow * 1024 + col]       = o0;
            *(float2*)&E[(size_t)(mrow + 8) * 1024 + col] = o1;
        }
    }
}

// ---------------------------------------------------------------------------
__global__ void h0_to_bf16(const float* __restrict__ h0)
{
    int i = blockIdx.x * 256 + threadIdx.x;
    g_hbf[1][i] = __float2bfloat16(h0[i]);
}

// Dummy launch: shifts ncu's fixed capture slot onto rnn_persistent.
__global__ void ncu_shift_dummy() {}

// ---------------------------------------------------------------------------
// Per-m-group barrier: 16 CTAs, release/acquire atomics, monotonic counter.
// ---------------------------------------------------------------------------
__device__ __forceinline__ void group_barrier(int grp, unsigned target)
{
    __syncthreads();
    if (threadIdx.x == 0) {
        unsigned* ctr = &g_grp[grp][0];
        asm volatile("red.release.gpu.global.add.u32 [%0], %1;"
                     :: "l"(ctr), "r"(1u) : "memory");
        unsigned v;
        do {
            asm volatile("ld.acquire.gpu.global.u32 %0, [%1];"
                         : "=r"(v) : "l"(ctr) : "memory");
        } while (v < target);
    }
    __syncthreads();
}

// ---------------------------------------------------------------------------
// Persistent recurrence, R10: R8 shell (128 CTAs, 32m x 64n, bulk staging,
// one sync) + SPLIT-K warp specialization. Warp w = (nh = w&1, kq = w>>1)
// computes a 32m x 32n x 256k partial: A and B fragments each feed 4 MMAs
// (vs 1-2 in R8), cutting MMA-phase LDS bytes in half. fp32 k-partials are
// exchanged through the As buffer (reused after MMA reads complete) and
// reduced in the epilogue.
// smem: Ws 128KB + As 64KB (h tile, then reduction buffer) = 192KB.
// ---------------------------------------------------------------------------
__global__ void __launch_bounds__(256, 1)
rnn_persistent(const float* __restrict__ W_h,
               const float* __restrict__ b_h)
{
    extern __shared__ unsigned smw[];
    unsigned* Ws = smw;              // 32768 words (128KB)
    unsigned* As = smw + 32768;      // 16384 words (64KB)
    float*    Red = (float*)As;      // reduction buffer (reuses As)

    const int tid  = threadIdx.x;
    const int lane = tid & 31;
    const int w    = tid >> 5;
    const int qid  = lane >> 2;
    const int c    = lane & 3;
    const int mw   = (w >> 2) * 16;  // epilogue coords (R8 mapping)
    const int nw   = (w & 3) * 16;
    const int nh   = w & 1;          // MMA role: n-half (32 cols)
    const int kq   = w >> 1;         // MMA role: k-quarter (256 k)
    const int cta  = blockIdx.x;
    const int grp  = cta >> 4;
    const int m0   = grp * MT;
    const int n0   = (cta & 15) * NT;

    // ---- fill Ws (once): fp32 -> bf16x2, fragment-shuffled (R8 layout) ----
    for (int i = tid; i < NT * 512; i += 256) {
        int n  = i >> 9;
        int kp = i & 511;
        int k  = kp * 2;
        int s  = k >> 4;
        int p  = (k & 15) >> 1;
        float2 wv = *(const float2*)(W_h + (size_t)(n0 + n) * HID + k);
        __nv_bfloat162 bb = __float22bfloat162_rn(wv);
        Ws[s * 512 + n * 8 + (p & 3) * 2 + (p >> 2)] = *(unsigned*)&bb;
    }
    const float2 bh0 = *(const float2*)(b_h + n0 + nw + 2 * c);
    const float2 bh1 = *(const float2*)(b_h + n0 + nw + 8 + 2 * c);
    __syncthreads();

    const int srow = tid >> 3;
    const int ssl  = tid & 7;
    const int sx   = ssl & 3;

    for (int t = 0; t < T_STEPS; t++) {
        const __nv_bfloat16* hin  = g_hbf[(t + 1) & 1];
        __nv_bfloat16*       hout = g_hbf[t & 1];

        // ---- bulk load: whole h tile, 16 int4 per thread, front-batched ----
        const __nv_bfloat16* gsrc = hin + (size_t)(m0 + srow) * HID + ssl * 16;
        int4 v[16];
        #pragma unroll
        for (int ch = 0; ch < 8; ch++) {
            v[2 * ch]     = __ldcg((const int4*)(gsrc + ch * 128));
            v[2 * ch + 1] = __ldcg((const int4*)(gsrc + ch * 128 + 8));
        }

        // epilogue operands (overlap with h loads)
        const float* eb = g_E + ((size_t)t * BATCH + m0 + mw + qid) * HID
                              + n0 + nw + 2 * c;
        float2 e00 = __ldg((const float2*)eb);
        float2 e01 = __ldg((const float2*)(eb + 8));
        float2 e10 = __ldg((const float2*)(eb + 8 * HID));
        float2 e11 = __ldg((const float2*)(eb + 8 * HID + 8));

        // ---- stage all 8 chunks, one sync ----
        #pragma unroll
        for (int ch = 0; ch < 8; ch++) {
            uint2* dp = (uint2*)(As + ch * 2048 + ssl * 256 + srow * 8);
            int4 a = v[2 * ch], b = v[2 * ch + 1];
            dp[0 ^ sx] = make_uint2(a.x, b.x);
            dp[1 ^ sx] = make_uint2(a.y, b.y);
            dp[2 ^ sx] = make_uint2(a.z, b.z);
            dp[3 ^ sx] = make_uint2(a.w, b.w);
        }
        __syncthreads();

        // ---- MMA phase: warp = (nh, kq); 16 k16-slices, 8 MMAs each ----
        float d[2][4][4];
        #pragma unroll
        for (int mg = 0; mg < 2; mg++)
            #pragma unroll
            for (int ng = 0; ng < 4; ng++)
                #pragma unroll
                for (int j = 0; j < 4; j++) d[mg][ng][j] = 0.0f;

        #pragma unroll
        for (int i = 0; i < 16; i++) {
            const int s = kq * 16 + i;
            const unsigned* Ab = As + s * 256 + 2 * (c ^ (s & 3));
            uint2 a0L = *(const uint2*)(Ab + qid * 8);           // rows qid
            uint2 a0H = *(const uint2*)(Ab + (qid + 8) * 8);     // rows qid+8
            uint2 a1L = *(const uint2*)(Ab + (qid + 16) * 8);    // rows qid+16
            uint2 a1H = *(const uint2*)(Ab + (qid + 24) * 8);    // rows qid+24
            const unsigned* Wb = Ws + s * 512 + (nh * 32 + qid) * 8 + 2 * c;
            uint2 b0 = *(const uint2*)(Wb);                      // n8 group 0
            uint2 b1 = *(const uint2*)(Wb + 64);                 // +8
            uint2 b2 = *(const uint2*)(Wb + 128);                // +16
            uint2 b3 = *(const uint2*)(Wb + 192);                // +24
            mma_bf16(d[0][0], a0L.x, a0H.x, a0L.y, a0H.y, b0.x, b0.y);
            mma_bf16(d[0][1], a0L.x, a0H.x, a0L.y, a0H.y, b1.x, b1.y);
            mma_bf16(d[0][2], a0L.x, a0H.x, a0L.y, a0H.y, b2.x, b2.y);
            mma_bf16(d[0][3], a0L.x, a0H.x, a0L.y, a0H.y, b3.x, b3.y);
            mma_bf16(d[1][0], a1L.x, a1H.x, a1L.y, a1H.y, b0.x, b0.y);
            mma_bf16(d[1][1], a1L.x, a1H.x, a1L.y, a1H.y, b1.x, b1.y);
            mma_bf16(d[1][2], a1L.x, a1H.x, a1L.y, a1H.y, b2.x, b2.y);
            mma_bf16(d[1][3], a1L.x, a1H.x, a1L.y, a1H.y, b3.x, b3.y);
        }
        __syncthreads();   // all As (h tile) reads complete

        // ---- write fp32 k-partials into Red (reuses As) ----
        #pragma unroll
        for (int mg = 0; mg < 2; mg++) {
            #pragma unroll
            for (int ng = 0; ng < 4; ng++) {
                float* rp = Red + kq * RKQ + (mg * 16 + qid) * RSTR
                          + nh * 32 + ng * 8 + 2 * c;
                *(float2*)rp             = make_float2(d[mg][ng][0], d[mg][ng][1]);
                *(float2*)(rp + 8 * RSTR) = make_float2(d[mg][ng][2], d[mg][ng][3]);
            }
        }
        __syncthreads();

        // ---- epilogue: reduce 4 k-partials, + b_h + E, sigmoid ----
        const int ml = mw + qid;
        const int nl = nw + 2 * c;
        const float* r0 = Red + ml * RSTR + nl;
        float2 f00, f01, f10, f11;
        {
            float2 p0 = *(const float2*)(r0);
            float2 p1 = *(const float2*)(r0 + RKQ);
            float2 p2 = *(const float2*)(r0 + 2 * RKQ);
            float2 p3 = *(const float2*)(r0 + 3 * RKQ);
            f00.x = (p0.x + p1.x) + (p2.x + p3.x);
            f00.y = (p0.y + p1.y) + (p2.y + p3.y);
        }
        {
            const float* r = r0 + 8;
            float2 p0 = *(const float2*)(r);
            float2 p1 = *(const float2*)(r + RKQ);
            float2 p2 = *(const float2*)(r + 2 * RKQ);
            float2 p3 = *(const float2*)(r + 3 * RKQ);
            f01.x = (p0.x + p1.x) + (p2.x + p3.x);
            f01.y = (p0.y + p1.y) + (p2.y + p3.y);
        }
        {
            const float* r = r0 + 8 * RSTR;
            float2 p0 = *(const float2*)(r);
            float2 p1 = *(const float2*)(r + RKQ);
            float2 p2 = *(const float2*)(r + 2 * RKQ);
            float2 p3 = *(const float2*)(r + 3 * RKQ);
            f10.x = (p0.x + p1.x) + (p2.x + p3.x);
            f10.y = (p0.y + p1.y) + (p2.y + p3.y);
        }
        {
            const float* r = r0 + 8 * RSTR + 8;
            float2 p0 = *(const float2*)(r);
            float2 p1 = *(const float2*)(r + RKQ);
            float2 p2 = *(const float2*)(r + 2 * RKQ);
            float2 p3 = *(const float2*)(r + 3 * RKQ);
            f11.x = (p0.x + p1.x) + (p2.x + p3.x);
            f11.y = (p0.y + p1.y) + (p2.y + p3.y);
        }

        float s00x = sigmoidf_fast(f00.x + bh0.x + e00.x);
        float s00y = sigmoidf_fast(f00.y + bh0.y + e00.y);
        float s10x = sigmoidf_fast(f10.x + bh0.x + e10.x);
        float s10y = sigmoidf_fast(f10.y + bh0.y + e10.y);
        float s01x = sigmoidf_fast(f01.x + bh1.x + e01.x);
        float s01y = sigmoidf_fast(f01.y + bh1.y + e01.y);
        float s11x = sigmoidf_fast(f11.x + bh1.x + e11.x);
        float s11y = sigmoidf_fast(f11.y + bh1.y + e11.y);

        __nv_bfloat16* ho = hout + (size_t)(m0 + ml) * HID + n0 + nl;
        *(__nv_bfloat162*)(ho)               = __float22bfloat162_rn(make_float2(s00x, s00y));
        *(__nv_bfloat162*)(ho + 8)           = __float22bfloat162_rn(make_float2(s01x, s01y));
        *(__nv_bfloat162*)(ho + 8 * HID)     = __float22bfloat162_rn(make_float2(s10x, s10y));
        *(__nv_bfloat162*)(ho + 8 * HID + 8) = __float22bfloat162_rn(make_float2(s11x, s11y));

        if (t == T_STEPS - 1) {
            float* hf = g_hfinal + (size_t)(m0 + ml) * HID + n0 + nl;
            *(float2*)(hf)               = make_float2(s00x, s00y);
            *(float2*)(hf + 8)           = make_float2(s01x, s01y);
            *(float2*)(hf + 8 * HID)     = make_float2(s10x, s10y);
            *(float2*)(hf + 8 * HID + 8) = make_float2(s11x, s11y);
        } else {
            group_barrier(grp, 16u * (t + 1));
        }
    }
}

// ---------------------------------------------------------------------------
// Final head (all 128 threads participate in the dot product)
// ---------------------------------------------------------------------------
__global__ void finalize_kernel(const float* __restrict__ h,
                                const float* __restrict__ state_in,
                                const float* __restrict__ W_o,
                                const float* __restrict__ b_o,
                                float* __restrict__ out)
{
    const int b    = blockIdx.x;
    const int tid  = threadIdx.x;
    const int lane = tid & 31;
    const int wid  = tid >> 5;

    __shared__ float red[4][OUTD];
    __shared__ float logits[OUTD];

    float acc[OUTD];
    #pragma unroll
    for (int o = 0; o < OUTD; o++) acc[o] = 0.0f;
    for (int k = tid; k < HID; k += 128) {
        float hv = h[(size_t)b * HID + k];
        #pragma unroll
        for (int o = 0; o < OUTD; o++)
            acc[o] += hv * W_o[(size_t)o * HID + k];
    }
    #pragma unroll
    for (int o = 0; o < OUTD; o++) {
        float v = acc[o];
        #pragma unroll
        for (int s = 16; s > 0; s >>= 1)
            v += __shfl_xor_sync(0xffffffff, v, s);
        if (lane == 0) red[wid][o] = v;
    }
    __syncthreads();

    if (tid == 0) {
        #pragma unroll
        for (int o = 0; o < OUTD; o++)
            logits[o] = red[0][o] + red[1][o] + red[2][o] + red[3][o] + b_o[o];
        float m = logits[0];
        #pragma unroll
        for (int o = 1; o < OUTD; o++) m = fmaxf(m, logits[o]);
        float s = 0.0f;
        #pragma unroll
        for (int o = 0; o < OUTD; o++) s += expf(logits[o] - m);
        float lse = m + logf(s);
        #pragma unroll
        for (int o = 0; o < OUTD; o++)
            out[(size_t)b * OUTD + o] = logits[o] - lse;
    }

    float* hid_out = out + (size_t)BATCH * OUTD;
    float* st_out  = hid_out + (size_t)BATCH * HID;
    for (int k = tid; k < HID; k += blockDim.x) {
        hid_out[(size_t)b * HID + k] = h[(size_t)b * HID + k];
        st_out[(size_t)b * HID + k]  = state_in[(size_t)b * HID + k];
    }
}

extern "C" void kernel_launch(void* const* d_in, const int* in_sizes, int n_in,
                              void* d_out, int out_size)
{
    const float* x    = (const float*)d_in[0];
    const float* h0   = (const float*)d_in[1];
    const float* st   = (const float*)d_in[2];
    const float* W_in = (const float*)d_in[3];
    const float* b_in = (const float*)d_in[4];
    const float* W_h  = (const float*)d_in[5];
    const float* b_h  = (const float*)d_in[6];
    const float* W_o  = (const float*)d_in[7];
    const float* b_o  = (const float*)d_in[8];
    float* out = (float*)d_out;

    float* Eptr = nullptr;
    float* hfin = nullptr;
    unsigned* grpptr = nullptr;
    cudaGetSymbolAddress((void**)&Eptr, g_E);
    cudaGetSymbolAddress((void**)&hfin, g_hfinal);
    cudaGetSymbolAddress((void**)&grpptr, g_grp);

    cudaMemsetAsync(grpptr, 0, 8 * 32 * sizeof(unsigned));

    // 0) h0 -> bf16 transport buffer
    h0_to_bf16<<<(BATCH * HID) / 256, 256>>>(h0);

    // 1) E = x @ W_in^T + b_in (single-pass bf16, fp32 accumulate)
    {
        const int smem_bytes = 12288 * sizeof(unsigned);  // 48KB
        cudaFuncSetAttribute(egemm_bf16,
                             cudaFuncAttributeMaxDynamicSharedMemorySize, smem_bytes);
        dim3 grid(HID / 64, (T_STEPS * BATCH) / 128);
        egemm_bf16<<<grid, 256, smem_bytes>>>(x, W_in, b_in, Eptr);
    }

    // 1.5) shift ncu's capture slot onto rnn_persistent
    ncu_shift_dummy<<<1, 32>>>();

    // 2) Persistent recurrence (R10: split-K warps, halved LDS traffic)
    {
        const int smem_bytes = (32768 + 16384) * sizeof(unsigned);  // 192KB
        cudaFuncSetAttribute(rnn_persistent,
                             cudaFuncAttributeMaxDynamicSharedMemorySize, smem_bytes);
        rnn_persistent<<<GRID_P, 256, smem_bytes>>>(W_h, b_h);
    }

    // 3) Head + output tuple
    finalize_kernel<<<BATCH, 128>>>(hfin, st, W_o, b_o, out);
}